// round 11
// baseline (speedup 1.0000x reference)
#include <cuda_runtime.h>
#include <math.h>

#define NSEG 4
#define NPIX 256
#define NTHR 1024
#define TSX 16
#define TSY 16
#define NB  148
#define MAXNV 64
#define CHK 16                 // entries per segment per round (64/round total)

// Monotonic per-view work-queue tickets (replay-safe: each launch consumes
// exactly tilesPerView + blocksPerView tickets per view; never reset).
__device__ unsigned int g_q[MAXNV];

// ---------------------------------------------------------------------------
// Single kernel. Each block serves ONE view: preps all G gaussians into smem
// once, then dynamically grabs tiles (cull -> warp rank sort -> chunked blend
// with block-wide early exit).
// ---------------------------------------------------------------------------
__global__ __launch_bounds__(NTHR, 1)
void splat_kernel(float* __restrict__ out,
                  const float* __restrict__ means,
                  const float* __restrict__ scales,
                  const float* __restrict__ rots,
                  const float* __restrict__ sh,
                  const float* __restrict__ opac,
                  const float* __restrict__ extr,
                  const float* __restrict__ intr,
                  const int* __restrict__ Hp,
                  const int* __restrict__ Wp,
                  int G, int NV)
{
    int W = *Wp, H = *Hp;
    int ntx = (W + TSX - 1) / TSX, nty = (H + TSY - 1) / TSY;
    int tilesPerView = ntx * nty;
    int tid = threadIdx.x;
    int lane = tid & 31;
    int wid = tid >> 5;

    extern __shared__ char dsm[];
    float4* s_pos = (float4*)dsm;                   // (u, v, thr, z)   G*16
    float4* s_con = s_pos + G;                      // (ca, cb, cc, op) G*16
    float4* s_col = s_con + G;                      // (cr, cg, cb, -)  G*16
    float*  s_rad = (float*)(s_col + G);            // cull radius      G*4
    unsigned long long* s_key = (unsigned long long*)(s_rad + G);  // G*8
    int* s_sid = (int*)(s_key + G);                 // sorted order     G*4
    __shared__ float4 segC[NSEG][NPIX];
    __shared__ float  segT[NSEG][NPIX];
    __shared__ float4 accC[NPIX];
    __shared__ float  accT[NPIX];
    __shared__ int s_cnt;
    __shared__ int s_tile;

    for (int vi = 0; vi < NV; vi++) {
        int b0 = (int)((long long)vi * NB / NV);
        int b1 = (int)((long long)(vi + 1) * NB / NV);
        if ((int)blockIdx.x < b0 || (int)blockIdx.x >= b1) continue;
        int nbv = b1 - b0;
        unsigned int M = (unsigned int)(tilesPerView + nbv);  // ticket window

        const float* E = extr + vi * 16;
        const float* K = intr + vi * 9;
        float Wf = (float)W, Hf = (float)H;
        float fx = (K[0] / Wf) * Wf;
        float cx = (K[2] / Wf) * Wf;
        float fy = (K[4] / Hf) * Hf;
        float cy = (K[5] / Hf) * Hf;

        // ================= Phase A: prep all G gaussians into smem =========
        for (int g = tid; g < G; g += NTHR) {
            float mx = means[g*3+0], my = means[g*3+1], mz = means[g*3+2];
            float px = E[0]*mx + E[1]*my + E[2]*mz  + E[3];
            float py = E[4]*mx + E[5]*my + E[6]*mz  + E[7];
            float pz = E[8]*mx + E[9]*my + E[10]*mz + E[11];
            float zs = fmaxf(pz, 1e-6f);
            float iz = 1.0f / zs;
            float u = fx * px * iz + cx;
            float v = fy * py * iz + cy;

            float4 q4 = ((const float4*)rots)[g];
            float qw = q4.x, qx = q4.y, qy = q4.z, qz = q4.w;
            float qinv = rsqrtf(qw*qw + qx*qx + qy*qy + qz*qz);
            qw *= qinv; qx *= qinv; qy *= qinv; qz *= qinv;
            float R00 = 1.f - 2.f*(qy*qy + qz*qz), R01 = 2.f*(qx*qy - qw*qz), R02 = 2.f*(qx*qz + qw*qy);
            float R10 = 2.f*(qx*qy + qw*qz), R11 = 1.f - 2.f*(qx*qx + qz*qz), R12 = 2.f*(qy*qz - qw*qx);
            float R20 = 2.f*(qx*qz - qw*qy), R21 = 2.f*(qy*qz + qw*qx), R22 = 1.f - 2.f*(qx*qx + qy*qy);

            float s0 = scales[g*3+0], s1 = scales[g*3+1], s2 = scales[g*3+2];
            float M00=R00*s0, M01=R01*s1, M02=R02*s2;
            float M10=R10*s0, M11=R11*s1, M12=R12*s2;
            float M20=R20*s0, M21=R21*s1, M22=R22*s2;
            float S00 = M00*M00+M01*M01+M02*M02;
            float S01 = M00*M10+M01*M11+M02*M12;
            float S02 = M00*M20+M01*M21+M02*M22;
            float S11 = M10*M10+M11*M11+M12*M12;
            float S12 = M10*M20+M11*M21+M12*M22;
            float S22 = M20*M20+M21*M21+M22*M22;

            float J00 = fx*iz,  J02 = -fx*px*iz*iz;
            float J11 = fy*iz,  J12 = -fy*py*iz*iz;
            float t00 = J00*E[0] + J02*E[8];
            float t01 = J00*E[1] + J02*E[9];
            float t02 = J00*E[2] + J02*E[10];
            float t10 = J11*E[4] + J12*E[8];
            float t11 = J11*E[5] + J12*E[9];
            float t12 = J11*E[6] + J12*E[10];
            float w0 = S00*t00 + S01*t01 + S02*t02;
            float w1 = S01*t00 + S11*t01 + S12*t02;
            float w2 = S02*t00 + S12*t01 + S22*t02;
            float a  = t00*w0 + t01*w1 + t02*w2 + 0.3f;
            float b  = t10*w0 + t11*w1 + t12*w2;
            float x0 = S00*t10 + S01*t11 + S02*t12;
            float x1 = S01*t10 + S11*t11 + S12*t12;
            float x2 = S02*t10 + S12*t11 + S22*t12;
            float d  = t10*x0 + t11*x1 + t12*x2 + 0.3f;

            float det = a*d - b*b;
            float ds  = fmaxf(det, 1e-12f);
            float ids = 1.0f / ds;
            bool valid = (pz > 0.2f) && (det > 1e-12f);
            float op = valid ? opac[g] : 0.f;

            const float SH_C0 = 0.28209479177387814f;
            float cr  = fmaxf(SH_C0 * sh[g*3+0] + 0.5f, 0.f);
            float cg  = fmaxf(SH_C0 * sh[g*3+1] + 0.5f, 0.f);
            float cbl = fmaxf(SH_C0 * sh[g*3+2] + 0.5f, 0.f);

            float rad = -1.f, thr = 0.f;
            if (op * 255.f > 1.f) {
                float lam = 0.5f*(a+d) + sqrtf(0.25f*(a-d)*(a-d) + b*b);
                float t = __logf(255.f * op);
                rad = sqrtf(fmaxf(2.f*t*lam, 0.f)) + 0.05f;
                thr = -t - 1e-4f;   // power < thr => alpha < 1/255 guaranteed
            }

            s_pos[g] = make_float4(u, v, thr, pz);
            s_con[g] = make_float4(-0.5f*d*ids, b*ids, -0.5f*a*ids, op);
            s_col[g] = make_float4(cr, cg, cbl, 0.f);
            s_rad[g] = rad;
        }
        __syncthreads();

        // ================= Phase B: dynamic tile queue =====================
        int seg = tid >> 8, pix = tid & (NPIX - 1);
        int lx = pix & (TSX - 1), ly = pix >> 4;

        while (true) {
            __syncthreads();
            if (tid == 0) {
                unsigned int tk = atomicAdd(&g_q[vi], 1u);
                s_tile = (int)(tk % M);        // >= tilesPerView -> exit ticket
                s_cnt = 0;
            }
            __syncthreads();
            int t2 = s_tile;
            if (t2 >= tilesPerView) break;

            int tx = t2 % ntx, ty = t2 / ntx;
            float tminx = (float)(tx*TSX), tmaxx = (float)(tx*TSX + TSX);
            float tminy = (float)(ty*TSY), tmaxy = (float)(ty*TSY + TSY);

            // ---- cull from smem: append (flipped z | idx) keys ----
            for (int g = tid; g < G; g += NTHR) {
                float4 p = s_pos[g];
                float rad = s_rad[g];
                bool keep = (rad > 0.f &&
                             p.x >= tminx - rad && p.x <= tmaxx + rad &&
                             p.y >= tminy - rad && p.y <= tmaxy + rad);
                unsigned m = __ballot_sync(0xffffffffu, keep);
                if (m) {
                    int leader = __ffs(m) - 1;
                    int basep = 0;
                    if (lane == leader) basep = atomicAdd(&s_cnt, __popc(m));
                    basep = __shfl_sync(0xffffffffu, basep, leader);
                    if (keep) {
                        unsigned int zb = __float_as_uint(p.w);
                        zb = (zb & 0x80000000u) ? ~zb : (zb | 0x80000000u);
                        int pp = basep + __popc(m & ((1u << lane) - 1u));
                        s_key[pp] = ((unsigned long long)zb << 32) | (unsigned int)g;
                    }
                }
            }
            __syncthreads();
            int cnt = s_cnt;

            // ---- warp-parallel exact rank sort (unique keys) ----
            for (int i = wid; i < cnt; i += 32) {
                unsigned long long k = s_key[i];
                int r = 0;
                for (int j = lane; j < cnt; j += 32) r += (s_key[j] < k);
                r = __reduce_add_sync(0xffffffffu, r);
                if (lane == 0) s_sid[r] = (int)(unsigned int)k;
            }
            // init accumulators (no extra barrier: accX only touched below)
            if (seg == 0) {
                accC[pix] = make_float4(0.f, 0.f, 0.f, 0.f);
                accT[pix] = 1.f;
            }
            __syncthreads();

            // ---- chunked segment-parallel blend + block-wide early exit ----
            float pcx = (float)(tx*TSX + lx) + 0.5f;
            float pcy = (float)(ty*TSY + ly) + 0.5f;

            for (int pos = 0; pos < cnt; pos += NSEG * CHK) {
                int j0 = pos + seg * CHK;
                int j1 = min(j0 + CHK, cnt);

                float T = 1.f, ar = 0.f, ag = 0.f, ab = 0.f, ad = 0.f;
                for (int j = j0; j < j1; j++) {
                    int idx = s_sid[j];                 // broadcast LDS
                    float4 p  = s_pos[idx];
                    float4 cn = s_con[idx];
                    float du = pcx - p.x, dv = pcy - p.y;
                    float power = fmaf(cn.x, du*du, fmaf(cn.z, dv*dv, cn.y*du*dv));
                    if (power < p.z) continue;          // alpha < 1/255 guaranteed
                    power = fminf(power, 0.f);
                    float alpha = fminf(cn.w * __expf(power), 0.99f);
                    if (alpha >= (1.0f/255.0f)) {
                        float4 cl = s_col[idx];
                        float w = alpha * T;
                        ar += w * cl.x; ag += w * cl.y; ab += w * cl.z;
                        ad += w * p.w;
                        T *= (1.f - alpha);
                    }
                }
                segC[seg][pix] = make_float4(ar, ag, ab, ad);
                segT[seg][pix] = T;
                __syncthreads();

                // ordered combine into per-pixel accumulators (seg0 only)
                if (seg == 0) {
                    float4 C = accC[pix];
                    float Tacc = accT[pix];
                    #pragma unroll
                    for (int s = 0; s < NSEG; s++) {
                        float4 Cs = segC[s][pix];
                        C.x += Tacc * Cs.x; C.y += Tacc * Cs.y;
                        C.z += Tacc * Cs.z; C.w += Tacc * Cs.w;
                        Tacc *= segT[s][pix];
                    }
                    accC[pix] = C;
                    accT[pix] = Tacc;
                }
                __syncthreads();
                // block-wide early exit: residual bounded by accT < 1e-4
                if (__syncthreads_and(accT[pix] < 1e-4f)) break;
            }

            // ---- store ----
            if (seg == 0) {
                int px = tx*TSX + lx, py = ty*TSY + ly;
                if (px < W && py < H) {
                    ((float4*)out)[(vi * H + py) * W + px] = accC[pix];
                }
            }
        }
        break;   // each block serves exactly one view
    }
}

// ---------------------------------------------------------------------------
extern "C" void kernel_launch(void* const* d_in, const int* in_sizes, int n_in,
                              void* d_out, int out_size)
{
    const float* means  = (const float*)d_in[0];
    const float* scales = (const float*)d_in[1];
    const float* rots   = (const float*)d_in[2];
    const float* sh     = (const float*)d_in[3];
    const float* opac   = (const float*)d_in[4];
    const float* extr   = (const float*)d_in[5];
    const float* intr   = (const float*)d_in[6];
    const int*   Hp     = (const int*)d_in[7];
    const int*   Wp     = (const int*)d_in[8];
    float* out = (float*)d_out;

    int G  = in_sizes[4];        // B = 1 for this instance
    int NV = in_sizes[5] / 16;   // B*N views

    size_t dynSmem = (size_t)G * 64;
    static int attrSet = 0;
    if (!attrSet) {
        cudaFuncSetAttribute(splat_kernel,
                             cudaFuncAttributeMaxDynamicSharedMemorySize,
                             (int)dynSmem);
        attrSet = 1;
    }
    splat_kernel<<<NB, NTHR, dynSmem>>>(out, means, scales, rots, sh, opac,
                                        extr, intr, Hp, Wp, G, NV);
}

// round 12
// speedup vs baseline: 1.0100x; 1.0100x over previous
#include <cuda_runtime.h>
#include <math.h>

#define NSEG 4
#define NPIX 256
#define NTHR 1024
#define TSX 16
#define TSY 16
#define NB  148
#define MAXNV 64
#define CAP (1 << 14)

// Persistent device state (zero-init once; kept replay-safe):
//  g_bar: monotonic grid-barrier ticket (each launch adds exactly NB arrivals)
//  g_q  : per-view tile-queue tickets (each launch consumes tilesPerView+nbv)
__device__ unsigned int g_bar;
__device__ unsigned int g_q[MAXNV];
__device__ float4 g_pos[CAP];   // (u, v, thr, z)
__device__ float4 g_con[CAP];   // (ca, cb, cc, op)
__device__ float4 g_col[CAP];   // (cr, cg, cb, -)
__device__ float  g_rad[CAP];   // cull radius

__global__ __launch_bounds__(NTHR, 1)
void splat_kernel(float* __restrict__ out,
                  const float* __restrict__ means,
                  const float* __restrict__ scales,
                  const float* __restrict__ rots,
                  const float* __restrict__ sh,
                  const float* __restrict__ opac,
                  const float* __restrict__ extr,
                  const float* __restrict__ intr,
                  const int* __restrict__ Hp,
                  const int* __restrict__ Wp,
                  int G, int NV)
{
    int W = *Wp, H = *Hp;
    int ntx = (W + TSX - 1) / TSX, nty = (H + TSY - 1) / TSY;
    int tilesPerView = ntx * nty;
    int tid = threadIdx.x;
    int lane = tid & 31;
    int wid = tid >> 5;
    float Wf = (float)W, Hf = (float)H;

    // =============== Phase 1: each (view,gaussian) prepped ONCE =============
    {
        int total = G * NV;
        int per = (total + NB - 1) / NB;          // ~28 items per block
        int i0 = blockIdx.x * per;
        int i1 = min(i0 + per, total);
        for (int i = i0 + tid; i < i1; i += NTHR) {
            int vi = i / G;
            int g  = i - vi * G;
            const float* E = extr + vi * 16;
            const float* K = intr + vi * 9;
            float fx = (K[0] / Wf) * Wf;
            float cx = (K[2] / Wf) * Wf;
            float fy = (K[4] / Hf) * Hf;
            float cy = (K[5] / Hf) * Hf;

            float mx = means[g*3+0], my = means[g*3+1], mz = means[g*3+2];
            float px = E[0]*mx + E[1]*my + E[2]*mz  + E[3];
            float py = E[4]*mx + E[5]*my + E[6]*mz  + E[7];
            float pz = E[8]*mx + E[9]*my + E[10]*mz + E[11];
            float zs = fmaxf(pz, 1e-6f);
            float iz = 1.0f / zs;
            float u = fx * px * iz + cx;
            float v = fy * py * iz + cy;

            float4 q4 = ((const float4*)rots)[g];
            float qw = q4.x, qx = q4.y, qy = q4.z, qz = q4.w;
            float qinv = rsqrtf(qw*qw + qx*qx + qy*qy + qz*qz);
            qw *= qinv; qx *= qinv; qy *= qinv; qz *= qinv;
            float R00 = 1.f - 2.f*(qy*qy + qz*qz), R01 = 2.f*(qx*qy - qw*qz), R02 = 2.f*(qx*qz + qw*qy);
            float R10 = 2.f*(qx*qy + qw*qz), R11 = 1.f - 2.f*(qx*qx + qz*qz), R12 = 2.f*(qy*qz - qw*qx);
            float R20 = 2.f*(qx*qz - qw*qy), R21 = 2.f*(qy*qz + qw*qx), R22 = 1.f - 2.f*(qx*qx + qy*qy);

            float s0 = scales[g*3+0], s1 = scales[g*3+1], s2 = scales[g*3+2];
            float M00=R00*s0, M01=R01*s1, M02=R02*s2;
            float M10=R10*s0, M11=R11*s1, M12=R12*s2;
            float M20=R20*s0, M21=R21*s1, M22=R22*s2;
            float S00 = M00*M00+M01*M01+M02*M02;
            float S01 = M00*M10+M01*M11+M02*M12;
            float S02 = M00*M20+M01*M21+M02*M22;
            float S11 = M10*M10+M11*M11+M12*M12;
            float S12 = M10*M20+M11*M21+M12*M22;
            float S22 = M20*M20+M21*M21+M22*M22;

            float J00 = fx*iz,  J02 = -fx*px*iz*iz;
            float J11 = fy*iz,  J12 = -fy*py*iz*iz;
            float t00 = J00*E[0] + J02*E[8];
            float t01 = J00*E[1] + J02*E[9];
            float t02 = J00*E[2] + J02*E[10];
            float t10 = J11*E[4] + J12*E[8];
            float t11 = J11*E[5] + J12*E[9];
            float t12 = J11*E[6] + J12*E[10];
            float w0 = S00*t00 + S01*t01 + S02*t02;
            float w1 = S01*t00 + S11*t01 + S12*t02;
            float w2 = S02*t00 + S12*t01 + S22*t02;
            float a  = t00*w0 + t01*w1 + t02*w2 + 0.3f;
            float b  = t10*w0 + t11*w1 + t12*w2;
            float x0 = S00*t10 + S01*t11 + S02*t12;
            float x1 = S01*t10 + S11*t11 + S12*t12;
            float x2 = S02*t10 + S12*t11 + S22*t12;
            float d  = t10*x0 + t11*x1 + t12*x2 + 0.3f;

            float det = a*d - b*b;
            float ds  = fmaxf(det, 1e-12f);
            float ids = 1.0f / ds;
            bool valid = (pz > 0.2f) && (det > 1e-12f);
            float op = valid ? opac[g] : 0.f;

            const float SH_C0 = 0.28209479177387814f;
            float cr  = fmaxf(SH_C0 * sh[g*3+0] + 0.5f, 0.f);
            float cg  = fmaxf(SH_C0 * sh[g*3+1] + 0.5f, 0.f);
            float cbl = fmaxf(SH_C0 * sh[g*3+2] + 0.5f, 0.f);

            float rad = -1.f, thr = 0.f;
            if (op * 255.f > 1.f) {
                float lam = 0.5f*(a+d) + sqrtf(0.25f*(a-d)*(a-d) + b*b);
                float t = __logf(255.f * op);
                rad = sqrtf(fmaxf(2.f*t*lam, 0.f)) + 0.05f;
                thr = -t - 1e-4f;   // power < thr => alpha < 1/255 guaranteed
            }

            g_pos[i] = make_float4(u, v, thr, pz);
            g_con[i] = make_float4(-0.5f*d*ids, b*ids, -0.5f*a*ids, op);
            g_col[i] = make_float4(cr, cg, cbl, 0.f);
            g_rad[i] = rad;
        }
    }

    // =============== Grid barrier (monotonic ticket; replay-safe) ============
    __syncthreads();
    if (tid == 0) {
        __threadfence();
        unsigned int ticket = atomicAdd(&g_bar, 1u);
        unsigned int target = (ticket / NB + 1u) * NB;
        volatile unsigned int* vb = &g_bar;
        while (*vb < target) { }
        __threadfence();
    }
    __syncthreads();

    // =============== Phase 2: per-view smem copy + tile loop =================
    extern __shared__ char dsm[];
    float4* s_pos = (float4*)dsm;                   // G*16
    float4* s_con = s_pos + G;                      // G*16
    float4* s_col = s_con + G;                      // G*16
    float*  s_rad = (float*)(s_col + G);            // G*4
    unsigned long long* s_key = (unsigned long long*)(s_rad + G);  // G*8
    int* s_sid = (int*)(s_key + G);                 // G*4
    __shared__ float4 segC[NSEG][NPIX];
    __shared__ float  segT[NSEG][NPIX];
    __shared__ int s_cnt;
    __shared__ int s_tile;

    for (int vi = 0; vi < NV; vi++) {
        int b0 = (int)((long long)vi * NB / NV);
        int b1 = (int)((long long)(vi + 1) * NB / NV);
        if ((int)blockIdx.x < b0 || (int)blockIdx.x >= b1) continue;
        int nbv = b1 - b0;
        unsigned int M = (unsigned int)(tilesPerView + nbv);
        int base = vi * G;

        // bulk copy this view's params into smem
        for (int g = tid; g < G; g += NTHR) {
            s_pos[g] = g_pos[base + g];
            s_con[g] = g_con[base + g];
            s_col[g] = g_col[base + g];
            s_rad[g] = g_rad[base + g];
        }
        __syncthreads();

        int seg = tid >> 8, pix = tid & (NPIX - 1);
        int lx = pix & (TSX - 1), ly = pix >> 4;

        while (true) {
            __syncthreads();
            if (tid == 0) {
                unsigned int tk = atomicAdd(&g_q[vi], 1u);
                s_tile = (int)(tk % M);        // >= tilesPerView -> exit ticket
                s_cnt = 0;
            }
            __syncthreads();
            int t2 = s_tile;
            if (t2 >= tilesPerView) break;

            int tx = t2 % ntx, ty = t2 / ntx;
            float tminx = (float)(tx*TSX), tmaxx = (float)(tx*TSX + TSX);
            float tminy = (float)(ty*TSY), tmaxy = (float)(ty*TSY + TSY);

            // ---- cull from smem: append (flipped z | idx) keys ----
            for (int g = tid; g < G; g += NTHR) {
                float rad = s_rad[g];
                float4 p = s_pos[g];
                bool keep = (rad > 0.f &&
                             p.x >= tminx - rad && p.x <= tmaxx + rad &&
                             p.y >= tminy - rad && p.y <= tmaxy + rad);
                unsigned m = __ballot_sync(0xffffffffu, keep);
                if (m) {
                    int leader = __ffs(m) - 1;
                    int basep = 0;
                    if (lane == leader) basep = atomicAdd(&s_cnt, __popc(m));
                    basep = __shfl_sync(0xffffffffu, basep, leader);
                    if (keep) {
                        unsigned int zb = __float_as_uint(p.w);
                        zb = (zb & 0x80000000u) ? ~zb : (zb | 0x80000000u);
                        int pp = basep + __popc(m & ((1u << lane) - 1u));
                        s_key[pp] = ((unsigned long long)zb << 32) | (unsigned int)g;
                    }
                }
            }
            __syncthreads();
            int cnt = s_cnt;

            // ---- warp-parallel exact rank sort (unique keys) ----
            for (int i = wid; i < cnt; i += 32) {
                unsigned long long k = s_key[i];
                int r = 0;
                for (int j = lane; j < cnt; j += 32) r += (s_key[j] < k);
                r = __reduce_add_sync(0xffffffffu, r);
                if (lane == 0) s_sid[r] = (int)(unsigned int)k;
            }
            __syncthreads();

            // ---- segment-parallel front-to-back blend ----
            float pcx = (float)(tx*TSX + lx) + 0.5f;
            float pcy = (float)(ty*TSY + ly) + 0.5f;
            int L = (cnt + NSEG - 1) / NSEG;
            int j0 = seg * L;
            int j1 = min(j0 + L, cnt);

            float T = 1.f, ar = 0.f, ag = 0.f, ab = 0.f, ad = 0.f;
            for (int j = j0; j < j1; j++) {
                int idx = s_sid[j];                 // broadcast LDS
                float4 p  = s_pos[idx];
                float4 cn = s_con[idx];
                float du = pcx - p.x, dv = pcy - p.y;
                float power = fmaf(cn.x, du*du, fmaf(cn.z, dv*dv, cn.y*du*dv));
                if (power < p.z) continue;          // alpha < 1/255 guaranteed
                power = fminf(power, 0.f);
                float alpha = fminf(cn.w * __expf(power), 0.99f);
                if (alpha >= (1.0f/255.0f)) {
                    float4 cl = s_col[idx];
                    float w = alpha * T;
                    ar += w * cl.x; ag += w * cl.y; ab += w * cl.z;
                    ad += w * p.w;
                    T *= (1.f - alpha);
                    if (T < 1e-5f) break;           // residual < 1e-5 absolute
                }
            }
            segC[seg][pix] = make_float4(ar, ag, ab, ad);
            segT[seg][pix] = T;
            __syncthreads();

            // ---- combine segments front-to-back + store ----
            if (seg == 0) {
                float4 C = segC[0][pix];
                float Tacc = segT[0][pix];
                #pragma unroll
                for (int s = 1; s < NSEG; s++) {
                    float4 Cs = segC[s][pix];
                    C.x += Tacc * Cs.x; C.y += Tacc * Cs.y;
                    C.z += Tacc * Cs.z; C.w += Tacc * Cs.w;
                    Tacc *= segT[s][pix];
                }
                int px = tx*TSX + lx, py = ty*TSY + ly;
                if (px < W && py < H) {
                    ((float4*)out)[(vi * H + py) * W + px] = C;
                }
            }
        }
        break;   // each block serves exactly one view
    }
}

// ---------------------------------------------------------------------------
extern "C" void kernel_launch(void* const* d_in, const int* in_sizes, int n_in,
                              void* d_out, int out_size)
{
    const float* means  = (const float*)d_in[0];
    const float* scales = (const float*)d_in[1];
    const float* rots   = (const float*)d_in[2];
    const float* sh     = (const float*)d_in[3];
    const float* opac   = (const float*)d_in[4];
    const float* extr   = (const float*)d_in[5];
    const float* intr   = (const float*)d_in[6];
    const int*   Hp     = (const int*)d_in[7];
    const int*   Wp     = (const int*)d_in[8];
    float* out = (float*)d_out;

    int G  = in_sizes[4];        // B = 1 for this instance
    int NV = in_sizes[5] / 16;   // B*N views

    size_t dynSmem = (size_t)G * 64;   // pos+con+col+rad+key+sid
    static int attrSet = 0;
    if (!attrSet) {
        cudaFuncSetAttribute(splat_kernel,
                             cudaFuncAttributeMaxDynamicSharedMemorySize,
                             (int)dynSmem);
        attrSet = 1;
    }
    splat_kernel<<<NB, NTHR, dynSmem>>>(out, means, scales, rots, sh, opac,
                                        extr, intr, Hp, Wp, G, NV);
}

// round 15
// speedup vs baseline: 1.1076x; 1.0967x over previous
#include <cuda_runtime.h>
#include <math.h>

#define NSEG 4
#define NPIX 256
#define NTHR 1024
#define TSX 16
#define TSY 16
#define NGRID 296

struct Cam {
    float E0,E1,E2,E3,E4,E5,E6,E7,E8,E9,E10,E11;
    float fx, fy, cx, cy;
};

struct CoreP {
    float u, v, z, rad;
    float a, b, d, op;
};

// Shared core: projection + 2D covariance + cull radius. Used (bit-identically)
// by both the cull pass and the gather pass.
__device__ __forceinline__ CoreP prep_core(
    int g, const float* __restrict__ means, const float* __restrict__ scales,
    const float* __restrict__ rots, const float* __restrict__ opac,
    const Cam& e)
{
    CoreP r;
    float mx = means[g*3+0], my = means[g*3+1], mz = means[g*3+2];
    float px = e.E0*mx + e.E1*my + e.E2*mz + e.E3;
    float py = e.E4*mx + e.E5*my + e.E6*mz + e.E7;
    float pz = e.E8*mx + e.E9*my + e.E10*mz + e.E11;
    float zs = fmaxf(pz, 1e-6f);
    float iz = 1.0f / zs;
    r.z = pz;
    r.u = e.fx * px * iz + e.cx;
    r.v = e.fy * py * iz + e.cy;

    float4 q4 = ((const float4*)rots)[g];
    float qw = q4.x, qx = q4.y, qy = q4.z, qz = q4.w;
    float qinv = rsqrtf(qw*qw + qx*qx + qy*qy + qz*qz);
    qw *= qinv; qx *= qinv; qy *= qinv; qz *= qinv;
    float R00 = 1.f - 2.f*(qy*qy + qz*qz), R01 = 2.f*(qx*qy - qw*qz), R02 = 2.f*(qx*qz + qw*qy);
    float R10 = 2.f*(qx*qy + qw*qz), R11 = 1.f - 2.f*(qx*qx + qz*qz), R12 = 2.f*(qy*qz - qw*qx);
    float R20 = 2.f*(qx*qz - qw*qy), R21 = 2.f*(qy*qz + qw*qx), R22 = 1.f - 2.f*(qx*qx + qy*qy);

    float s0 = scales[g*3+0], s1 = scales[g*3+1], s2 = scales[g*3+2];
    float M00=R00*s0, M01=R01*s1, M02=R02*s2;
    float M10=R10*s0, M11=R11*s1, M12=R12*s2;
    float M20=R20*s0, M21=R21*s1, M22=R22*s2;
    float S00 = M00*M00+M01*M01+M02*M02;
    float S01 = M00*M10+M01*M11+M02*M12;
    float S02 = M00*M20+M01*M21+M02*M22;
    float S11 = M10*M10+M11*M11+M12*M12;
    float S12 = M10*M20+M11*M21+M12*M22;
    float S22 = M20*M20+M21*M21+M22*M22;

    float J00 = e.fx*iz,  J02 = -e.fx*px*iz*iz;
    float J11 = e.fy*iz,  J12 = -e.fy*py*iz*iz;
    float t00 = J00*e.E0 + J02*e.E8;
    float t01 = J00*e.E1 + J02*e.E9;
    float t02 = J00*e.E2 + J02*e.E10;
    float t10 = J11*e.E4 + J12*e.E8;
    float t11 = J11*e.E5 + J12*e.E9;
    float t12 = J11*e.E6 + J12*e.E10;
    float w0 = S00*t00 + S01*t01 + S02*t02;
    float w1 = S01*t00 + S11*t01 + S12*t02;
    float w2 = S02*t00 + S12*t01 + S22*t02;
    float a  = t00*w0 + t01*w1 + t02*w2 + 0.3f;
    float b  = t10*w0 + t11*w1 + t12*w2;
    float x0 = S00*t10 + S01*t11 + S02*t12;
    float x1 = S01*t10 + S11*t11 + S12*t12;
    float x2 = S02*t10 + S12*t11 + S22*t12;
    float d  = t10*x0 + t11*x1 + t12*x2 + 0.3f;

    float det = a*d - b*b;
    bool valid = (r.z > 0.2f) && (det > 1e-12f);
    float op = valid ? opac[g] : 0.f;
    r.a = a; r.b = b; r.d = d; r.op = op;

    // conservative cull radius: alpha >= 1/255 requires
    // |delta| <= sqrt(2 ln(255 op) lmax(cov2D)); +0.05 fp safety margin
    float rad = -1.f;
    if (op * 255.f > 1.f) {
        float lam = 0.5f*(a+d) + sqrtf(0.25f*(a-d)*(a-d) + b*b);
        float t = __logf(255.f * op);
        rad = sqrtf(fmaxf(2.f*t*lam, 0.f)) + 0.05f;
    }
    r.rad = rad;
    return r;
}

// ---------------------------------------------------------------------------
// Single fused kernel: per-tile (trimmed prep + cull) -> warp rank sort ->
// gather (full prep, sorted order) -> segmented blend. One tile per block,
// grid-stride for generality.
// ---------------------------------------------------------------------------
__global__ __launch_bounds__(NTHR, 1)
void splat_kernel(float* __restrict__ out,
                  const float* __restrict__ means,
                  const float* __restrict__ scales,
                  const float* __restrict__ rots,
                  const float* __restrict__ sh,
                  const float* __restrict__ opac,
                  const float* __restrict__ extr,
                  const float* __restrict__ intr,
                  const int* __restrict__ Hp,
                  const int* __restrict__ Wp,
                  int G, int NV)
{
    int W = *Wp, H = *Hp;
    int ntx = (W + TSX - 1) / TSX, nty = (H + TSY - 1) / TSY;
    int totalTiles = ntx * nty * NV;

    extern __shared__ char dsm[];
    float4* s_pos = (float4*)dsm;                 // (u,v,thr,z)      G*16
    float4* s_con = s_pos + G;                    // (ca,cb,cc,op)    G*16
    float4* s_col = s_con + G;                    // (cr,cg,cb,-)     G*16
    unsigned long long* s_key = (unsigned long long*)(s_col + G);  // G*8
    int* s_sid = (int*)(s_key + G);               // G*4
    __shared__ float4 segC[NSEG][NPIX];
    __shared__ float  segT[NSEG][NPIX];
    __shared__ int s_cnt;

    int tid = threadIdx.x;
    int lane = tid & 31;
    int wid = tid >> 5;
    int seg = tid >> 8, pix = tid & (NPIX - 1);
    int lx = pix & (TSX - 1), ly = pix >> 4;
    float Wf = (float)W, Hf = (float)H;

    for (int tile = blockIdx.x; tile < totalTiles; tile += gridDim.x) {
        int vi = tile / (ntx * nty);
        int t2 = tile - vi * ntx * nty;
        int tx = t2 % ntx, ty = t2 / ntx;

        // hoist camera into registers (L1-hit loads, once per tile)
        const float* E = extr + vi * 16;
        const float* K = intr + vi * 9;
        Cam cam;
        cam.E0=E[0]; cam.E1=E[1]; cam.E2=E[2];  cam.E3=E[3];
        cam.E4=E[4]; cam.E5=E[5]; cam.E6=E[6];  cam.E7=E[7];
        cam.E8=E[8]; cam.E9=E[9]; cam.E10=E[10]; cam.E11=E[11];
        cam.fx = (K[0] / Wf) * Wf;
        cam.cx = (K[2] / Wf) * Wf;
        cam.fy = (K[4] / Hf) * Hf;
        cam.cy = (K[5] / Hf) * Hf;

        float tminx = (float)(tx*TSX), tmaxx = (float)(tx*TSX + TSX);
        float tminy = (float)(ty*TSY), tmaxy = (float)(ty*TSY + TSY);

        __syncthreads();
        if (tid == 0) s_cnt = 0;
        __syncthreads();

        // ---- trimmed prep + cull: append (flipped z | idx) keys ----
        for (int g = tid; g < G; g += NTHR) {
            CoreP p = prep_core(g, means, scales, rots, opac, cam);
            bool keep = (p.rad > 0.f &&
                         p.u >= tminx - p.rad && p.u <= tmaxx + p.rad &&
                         p.v >= tminy - p.rad && p.v <= tmaxy + p.rad);
            unsigned m = __ballot_sync(0xffffffffu, keep);
            if (m) {
                int leader = __ffs(m) - 1;
                int basep = 0;
                if (lane == leader) basep = atomicAdd(&s_cnt, __popc(m));
                basep = __shfl_sync(0xffffffffu, basep, leader);
                if (keep) {
                    unsigned int zb = __float_as_uint(p.z);
                    zb = (zb & 0x80000000u) ? ~zb : (zb | 0x80000000u);
                    int pp = basep + __popc(m & ((1u << lane) - 1u));
                    s_key[pp] = ((unsigned long long)zb << 32) | (unsigned int)g;
                }
            }
        }
        __syncthreads();
        int cnt = s_cnt;

        // ---- warp-parallel exact rank sort (unique keys) ----
        for (int i = wid; i < cnt; i += 32) {
            unsigned long long k = s_key[i];
            int r = 0;
            for (int j = lane; j < cnt; j += 32) r += (s_key[j] < k);
            r = __reduce_add_sync(0xffffffffu, r);
            if (lane == 0) s_sid[r] = (int)(unsigned int)k;
        }
        __syncthreads();

        // ---- gather: full prep for sorted survivors into smem ----
        for (int i = tid; i < cnt; i += NTHR) {
            int g = s_sid[i];
            CoreP p = prep_core(g, means, scales, rots, opac, cam);
            float det = p.a*p.d - p.b*p.b;
            float ids = 1.0f / fmaxf(det, 1e-12f);
            float t = __logf(255.f * p.op);       // survivors: op*255 > 1
            float thr = -t - 1e-4f;               // power < thr => skip exact
            const float SH_C0 = 0.28209479177387814f;
            float cr  = fmaxf(SH_C0 * sh[g*3+0] + 0.5f, 0.f);
            float cg  = fmaxf(SH_C0 * sh[g*3+1] + 0.5f, 0.f);
            float cbl = fmaxf(SH_C0 * sh[g*3+2] + 0.5f, 0.f);
            s_pos[i] = make_float4(p.u, p.v, thr, p.z);
            s_con[i] = make_float4(-0.5f*p.d*ids, p.b*ids, -0.5f*p.a*ids, p.op);
            s_col[i] = make_float4(cr, cg, cbl, 0.f);
        }
        __syncthreads();

        // ---- segment-parallel front-to-back blend (sequential smem) ----
        float pcx = (float)(tx*TSX + lx) + 0.5f;
        float pcy = (float)(ty*TSY + ly) + 0.5f;
        int L = (cnt + NSEG - 1) / NSEG;
        int j0 = seg * L;
        int j1 = min(j0 + L, cnt);

        float T = 1.f, ar = 0.f, ag = 0.f, ab = 0.f, ad = 0.f;
        for (int j = j0; j < j1; j++) {
            float4 p  = s_pos[j];
            float4 cn = s_con[j];
            float du = pcx - p.x, dv = pcy - p.y;
            float power = fmaf(cn.x, du*du, fmaf(cn.z, dv*dv, cn.y*du*dv));
            if (power < p.z) continue;            // alpha < 1/255 guaranteed
            power = fminf(power, 0.f);
            float alpha = fminf(cn.w * __expf(power), 0.99f);
            if (alpha >= (1.0f/255.0f)) {
                float4 cl = s_col[j];
                float w = alpha * T;
                ar += w * cl.x; ag += w * cl.y; ab += w * cl.z;
                ad += w * p.w;
                T *= (1.f - alpha);
                if (T < 1e-5f) break;             // residual < 1e-5 absolute
            }
        }
        segC[seg][pix] = make_float4(ar, ag, ab, ad);
        segT[seg][pix] = T;
        __syncthreads();

        // ---- combine segments front-to-back + store ----
        if (seg == 0) {
            float4 C = segC[0][pix];
            float Tacc = segT[0][pix];
            #pragma unroll
            for (int s = 1; s < NSEG; s++) {
                float4 Cs = segC[s][pix];
                C.x += Tacc * Cs.x; C.y += Tacc * Cs.y;
                C.z += Tacc * Cs.z; C.w += Tacc * Cs.w;
                Tacc *= segT[s][pix];
            }
            int px = tx*TSX + lx, py = ty*TSY + ly;
            if (px < W && py < H) {
                ((float4*)out)[(vi * H + py) * W + px] = C;
            }
        }
    }
}

// ---------------------------------------------------------------------------
extern "C" void kernel_launch(void* const* d_in, const int* in_sizes, int n_in,
                              void* d_out, int out_size)
{
    const float* means  = (const float*)d_in[0];
    const float* scales = (const float*)d_in[1];
    const float* rots   = (const float*)d_in[2];
    const float* sh     = (const float*)d_in[3];
    const float* opac   = (const float*)d_in[4];
    const float* extr   = (const float*)d_in[5];
    const float* intr   = (const float*)d_in[6];
    const int*   Hp     = (const int*)d_in[7];
    const int*   Wp     = (const int*)d_in[8];
    float* out = (float*)d_out;

    int G  = in_sizes[4];        // B = 1 for this instance
    int NV = in_sizes[5] / 16;   // B*N views

    size_t dynSmem = (size_t)G * (16 + 16 + 16 + 8 + 4);
    static int attrSet = 0;
    if (!attrSet) {
        cudaFuncSetAttribute(splat_kernel,
                             cudaFuncAttributeMaxDynamicSharedMemorySize,
                             (int)dynSmem);
        attrSet = 1;
    }
    splat_kernel<<<NGRID, NTHR, dynSmem>>>(out, means, scales, rots, sh, opac,
                                           extr, intr, Hp, Wp, G, NV);
}

// round 16
// speedup vs baseline: 1.2158x; 1.0976x over previous
#include <cuda_runtime.h>
#include <math.h>

#define NSEG 8
#define NPIXH 128            // threads per segment; each handles 2 pixels
#define NPIX 256
#define NTHR 1024
#define TSX 16
#define TSY 16
#define NGRID 296

struct Cam {
    float E0,E1,E2,E3,E4,E5,E6,E7,E8,E9,E10,E11;
    float fx, fy, cx, cy;
};

struct CoreP {
    float u, v, z, rad;
    float a, b, d, op;
};

// Shared core: projection + 2D covariance + cull radius. Used (bit-identically)
// by both the cull pass and the gather pass.
__device__ __forceinline__ CoreP prep_core(
    int g, const float* __restrict__ means, const float* __restrict__ scales,
    const float* __restrict__ rots, const float* __restrict__ opac,
    const Cam& e)
{
    CoreP r;
    float mx = means[g*3+0], my = means[g*3+1], mz = means[g*3+2];
    float px = e.E0*mx + e.E1*my + e.E2*mz + e.E3;
    float py = e.E4*mx + e.E5*my + e.E6*mz + e.E7;
    float pz = e.E8*mx + e.E9*my + e.E10*mz + e.E11;
    float zs = fmaxf(pz, 1e-6f);
    float iz = 1.0f / zs;
    r.z = pz;
    r.u = e.fx * px * iz + e.cx;
    r.v = e.fy * py * iz + e.cy;

    float4 q4 = ((const float4*)rots)[g];
    float qw = q4.x, qx = q4.y, qy = q4.z, qz = q4.w;
    float qinv = rsqrtf(qw*qw + qx*qx + qy*qy + qz*qz);
    qw *= qinv; qx *= qinv; qy *= qinv; qz *= qinv;
    float R00 = 1.f - 2.f*(qy*qy + qz*qz), R01 = 2.f*(qx*qy - qw*qz), R02 = 2.f*(qx*qz + qw*qy);
    float R10 = 2.f*(qx*qy + qw*qz), R11 = 1.f - 2.f*(qx*qx + qz*qz), R12 = 2.f*(qy*qz - qw*qx);
    float R20 = 2.f*(qx*qz - qw*qy), R21 = 2.f*(qy*qz + qw*qx), R22 = 1.f - 2.f*(qx*qx + qy*qy);

    float s0 = scales[g*3+0], s1 = scales[g*3+1], s2 = scales[g*3+2];
    float M00=R00*s0, M01=R01*s1, M02=R02*s2;
    float M10=R10*s0, M11=R11*s1, M12=R12*s2;
    float M20=R20*s0, M21=R21*s1, M22=R22*s2;
    float S00 = M00*M00+M01*M01+M02*M02;
    float S01 = M00*M10+M01*M11+M02*M12;
    float S02 = M00*M20+M01*M21+M02*M22;
    float S11 = M10*M10+M11*M11+M12*M12;
    float S12 = M10*M20+M11*M21+M12*M22;
    float S22 = M20*M20+M21*M21+M22*M22;

    float J00 = e.fx*iz,  J02 = -e.fx*px*iz*iz;
    float J11 = e.fy*iz,  J12 = -e.fy*py*iz*iz;
    float t00 = J00*e.E0 + J02*e.E8;
    float t01 = J00*e.E1 + J02*e.E9;
    float t02 = J00*e.E2 + J02*e.E10;
    float t10 = J11*e.E4 + J12*e.E8;
    float t11 = J11*e.E5 + J12*e.E9;
    float t12 = J11*e.E6 + J12*e.E10;
    float w0 = S00*t00 + S01*t01 + S02*t02;
    float w1 = S01*t00 + S11*t01 + S12*t02;
    float w2 = S02*t00 + S12*t01 + S22*t02;
    float a  = t00*w0 + t01*w1 + t02*w2 + 0.3f;
    float b  = t10*w0 + t11*w1 + t12*w2;
    float x0 = S00*t10 + S01*t11 + S02*t12;
    float x1 = S01*t10 + S11*t11 + S12*t12;
    float x2 = S02*t10 + S12*t11 + S22*t12;
    float d  = t10*x0 + t11*x1 + t12*x2 + 0.3f;

    float det = a*d - b*b;
    bool valid = (r.z > 0.2f) && (det > 1e-12f);
    float op = valid ? opac[g] : 0.f;
    r.a = a; r.b = b; r.d = d; r.op = op;

    // conservative cull radius: alpha >= 1/255 requires
    // |delta| <= sqrt(2 ln(255 op) lmax(cov2D)); +0.05 fp safety margin
    float rad = -1.f;
    if (op * 255.f > 1.f) {
        float lam = 0.5f*(a+d) + sqrtf(0.25f*(a-d)*(a-d) + b*b);
        float t = __logf(255.f * op);
        rad = sqrtf(fmaxf(2.f*t*lam, 0.f)) + 0.05f;
    }
    r.rad = rad;
    return r;
}

// ---------------------------------------------------------------------------
// Single fused kernel: per-tile prep+cull -> warp rank sort -> gather ->
// 8-segment blend with 2 vertically-paired pixels per thread.
// ---------------------------------------------------------------------------
__global__ __launch_bounds__(NTHR, 1)
void splat_kernel(float* __restrict__ out,
                  const float* __restrict__ means,
                  const float* __restrict__ scales,
                  const float* __restrict__ rots,
                  const float* __restrict__ sh,
                  const float* __restrict__ opac,
                  const float* __restrict__ extr,
                  const float* __restrict__ intr,
                  const int* __restrict__ Hp,
                  const int* __restrict__ Wp,
                  int G, int NV)
{
    int W = *Wp, H = *Hp;
    int ntx = (W + TSX - 1) / TSX, nty = (H + TSY - 1) / TSY;
    int totalTiles = ntx * nty * NV;

    extern __shared__ char dsm[];
    float4* s_pos = (float4*)dsm;                 // (u,v,thr,z)      G*16
    float4* s_con = s_pos + G;                    // (ca,cb,cc,op)    G*16
    float4* s_col = s_con + G;                    // (cr,cg,cb,-)     G*16
    unsigned long long* s_key = (unsigned long long*)(s_col + G);  // G*8
    int* s_sid = (int*)(s_key + G);               // G*4
    __shared__ float4 segC[NSEG][NPIX];           // per-segment partials (both pixels)
    __shared__ float  segT[NSEG][NPIX];
    __shared__ int s_cnt;

    int tid = threadIdx.x;
    int lane = tid & 31;
    int wid = tid >> 5;
    int seg = tid >> 7;              // 0..7
    int hp  = tid & (NPIXH - 1);     // 0..127
    int lx  = hp & (TSX - 1);
    int lyA = hp >> 4;               // 0..7 ; pixel B at lyA+8
    float Wf = (float)W, Hf = (float)H;

    for (int tile = blockIdx.x; tile < totalTiles; tile += gridDim.x) {
        int vi = tile / (ntx * nty);
        int t2 = tile - vi * ntx * nty;
        int tx = t2 % ntx, ty = t2 / ntx;

        // hoist camera into registers
        const float* E = extr + vi * 16;
        const float* K = intr + vi * 9;
        Cam cam;
        cam.E0=E[0]; cam.E1=E[1]; cam.E2=E[2];  cam.E3=E[3];
        cam.E4=E[4]; cam.E5=E[5]; cam.E6=E[6];  cam.E7=E[7];
        cam.E8=E[8]; cam.E9=E[9]; cam.E10=E[10]; cam.E11=E[11];
        cam.fx = (K[0] / Wf) * Wf;
        cam.cx = (K[2] / Wf) * Wf;
        cam.fy = (K[4] / Hf) * Hf;
        cam.cy = (K[5] / Hf) * Hf;

        float tminx = (float)(tx*TSX), tmaxx = (float)(tx*TSX + TSX);
        float tminy = (float)(ty*TSY), tmaxy = (float)(ty*TSY + TSY);

        __syncthreads();
        if (tid == 0) s_cnt = 0;
        __syncthreads();

        // ---- prep + cull: append (flipped z | idx) keys ----
        for (int g = tid; g < G; g += NTHR) {
            CoreP p = prep_core(g, means, scales, rots, opac, cam);
            bool keep = (p.rad > 0.f &&
                         p.u >= tminx - p.rad && p.u <= tmaxx + p.rad &&
                         p.v >= tminy - p.rad && p.v <= tmaxy + p.rad);
            unsigned m = __ballot_sync(0xffffffffu, keep);
            if (m) {
                int leader = __ffs(m) - 1;
                int basep = 0;
                if (lane == leader) basep = atomicAdd(&s_cnt, __popc(m));
                basep = __shfl_sync(0xffffffffu, basep, leader);
                if (keep) {
                    unsigned int zb = __float_as_uint(p.z);
                    zb = (zb & 0x80000000u) ? ~zb : (zb | 0x80000000u);
                    int pp = basep + __popc(m & ((1u << lane) - 1u));
                    s_key[pp] = ((unsigned long long)zb << 32) | (unsigned int)g;
                }
            }
        }
        __syncthreads();
        int cnt = s_cnt;

        // ---- warp-parallel exact rank sort (unique keys) ----
        for (int i = wid; i < cnt; i += 32) {
            unsigned long long k = s_key[i];
            int r = 0;
            for (int j = lane; j < cnt; j += 32) r += (s_key[j] < k);
            r = __reduce_add_sync(0xffffffffu, r);
            if (lane == 0) s_sid[r] = (int)(unsigned int)k;
        }
        __syncthreads();

        // ---- gather: full prep for sorted survivors into smem ----
        for (int i = tid; i < cnt; i += NTHR) {
            int g = s_sid[i];
            CoreP p = prep_core(g, means, scales, rots, opac, cam);
            float det = p.a*p.d - p.b*p.b;
            float ids = 1.0f / fmaxf(det, 1e-12f);
            float t = __logf(255.f * p.op);       // survivors: op*255 > 1
            float thr = -t - 1e-4f;               // power < thr => skip exact
            const float SH_C0 = 0.28209479177387814f;
            float cr  = fmaxf(SH_C0 * sh[g*3+0] + 0.5f, 0.f);
            float cg  = fmaxf(SH_C0 * sh[g*3+1] + 0.5f, 0.f);
            float cbl = fmaxf(SH_C0 * sh[g*3+2] + 0.5f, 0.f);
            s_pos[i] = make_float4(p.u, p.v, thr, p.z);
            s_con[i] = make_float4(-0.5f*p.d*ids, p.b*ids, -0.5f*p.a*ids, p.op);
            s_col[i] = make_float4(cr, cg, cbl, 0.f);
        }
        __syncthreads();

        // ---- 8-segment blend, 2 vertically-paired pixels per thread ----
        float pcx  = (float)(tx*TSX + lx) + 0.5f;
        float pcyA = (float)(ty*TSY + lyA) + 0.5f;
        int L = (cnt + NSEG - 1) / NSEG;
        int j0 = seg * L;
        int j1 = min(j0 + L, cnt);

        float T1 = 1.f, r1 = 0.f, g1 = 0.f, b1 = 0.f, d1 = 0.f;
        float T2 = 1.f, r2 = 0.f, g2 = 0.f, b2 = 0.f, d2 = 0.f;
        for (int j = j0; j < j1; j++) {
            float4 p  = s_pos[j];
            float4 cn = s_con[j];
            float du  = pcx - p.x;
            float dvA = pcyA - p.y;
            float dvB = dvA + 8.f;
            float base = cn.x * du * du;          // ca*du^2 (shared)
            float Bc   = cn.y * du;               // cb*du   (shared)
            float pw1 = fmaf(cn.z, dvA*dvA, fmaf(Bc, dvA, base));
            float pw2 = fmaf(cn.z, dvB*dvB, fmaf(Bc, dvB, base));
            if (pw1 < p.z && pw2 < p.z) continue; // both below 1/255: skip
            float4 cl = s_col[j];
            if (pw1 >= p.z) {
                float a1 = fminf(cn.w * __expf(fminf(pw1, 0.f)), 0.99f);
                if (a1 >= (1.0f/255.0f)) {
                    float w = a1 * T1;
                    r1 += w*cl.x; g1 += w*cl.y; b1 += w*cl.z; d1 += w*p.w;
                    T1 *= (1.f - a1);
                }
            }
            if (pw2 >= p.z) {
                float a2 = fminf(cn.w * __expf(fminf(pw2, 0.f)), 0.99f);
                if (a2 >= (1.0f/255.0f)) {
                    float w = a2 * T2;
                    r2 += w*cl.x; g2 += w*cl.y; b2 += w*cl.z; d2 += w*p.w;
                    T2 *= (1.f - a2);
                }
            }
            if (T1 < 1e-5f && T2 < 1e-5f) break;  // residual < 1e-5 absolute
        }
        segC[seg][lyA*16 + lx]      = make_float4(r1, g1, b1, d1);
        segT[seg][lyA*16 + lx]      = T1;
        segC[seg][(lyA+8)*16 + lx]  = make_float4(r2, g2, b2, d2);
        segT[seg][(lyA+8)*16 + lx]  = T2;
        __syncthreads();

        // ---- combine 8 segments front-to-back + store (256 threads) ----
        if (tid < NPIX) {
            int pixid = tid;
            float4 C = make_float4(0.f, 0.f, 0.f, 0.f);
            float Tacc = 1.f;
            #pragma unroll
            for (int s = 0; s < NSEG; s++) {
                float4 Cs = segC[s][pixid];
                C.x += Tacc * Cs.x; C.y += Tacc * Cs.y;
                C.z += Tacc * Cs.z; C.w += Tacc * Cs.w;
                Tacc *= segT[s][pixid];
            }
            int px = tx*TSX + (pixid & 15), py = ty*TSY + (pixid >> 4);
            if (px < W && py < H) {
                ((float4*)out)[(vi * H + py) * W + px] = C;
            }
        }
    }
}

// ---------------------------------------------------------------------------
extern "C" void kernel_launch(void* const* d_in, const int* in_sizes, int n_in,
                              void* d_out, int out_size)
{
    const float* means  = (const float*)d_in[0];
    const float* scales = (const float*)d_in[1];
    const float* rots   = (const float*)d_in[2];
    const float* sh     = (const float*)d_in[3];
    const float* opac   = (const float*)d_in[4];
    const float* extr   = (const float*)d_in[5];
    const float* intr   = (const float*)d_in[6];
    const int*   Hp     = (const int*)d_in[7];
    const int*   Wp     = (const int*)d_in[8];
    float* out = (float*)d_out;

    int G  = in_sizes[4];        // B = 1 for this instance
    int NV = in_sizes[5] / 16;   // B*N views

    size_t dynSmem = (size_t)G * (16 + 16 + 16 + 8 + 4);
    static int attrSet = 0;
    if (!attrSet) {
        cudaFuncSetAttribute(splat_kernel,
                             cudaFuncAttributeMaxDynamicSharedMemorySize,
                             (int)dynSmem);
        attrSet = 1;
    }
    splat_kernel<<<NGRID, NTHR, dynSmem>>>(out, means, scales, rots, sh, opac,
                                           extr, intr, Hp, Wp, G, NV);
}